// round 3
// baseline (speedup 1.0000x reference)
#include <cuda_runtime.h>
#include <math.h>

// Problem constants
#define BATCH 32
#define CIN   128
#define HH    56
#define WW    56
#define OUTC  128
#define HIDDEN 32
#define TEMPERATURE 31.0f
#define HWPIX (HH*WW)          // 3136

// Conv tiling
#define OT  32                 // output channels per block
#define TH  4                  // output rows per block
#define CCH 8                  // input channels per SMEM chunk
#define TPB (WW*TH)            // 224 threads

__device__ float g_attn[BATCH][2];

// ---------------------------------------------------------------------------
// Packed fp32x2 helpers (sm_103a). ptxas never emits FFMA2 from C++.
// ---------------------------------------------------------------------------
__device__ __forceinline__ unsigned long long bcast2(float v) {
    unsigned long long r;
    asm("mov.b64 %0, {%1, %1};" : "=l"(r) : "r"(__float_as_uint(v)));
    return r;
}
__device__ __forceinline__ void fma2(unsigned long long& d,
                                     unsigned long long a,
                                     unsigned long long b) {
    asm("fma.rn.f32x2 %0, %1, %2, %0;" : "+l"(d) : "l"(a), "l"(b));
}
__device__ __forceinline__ void unpack2(unsigned long long v, float& lo, float& hi) {
    asm("mov.b64 {%0, %1}, %2;" : "=f"(lo), "=f"(hi) : "l"(v));
}

// ---------------------------------------------------------------------------
// Kernel 1: global-avg-pool -> fc1(relu) -> fc2 -> softmax(./T)
// ---------------------------------------------------------------------------
__global__ void attn_kernel(const float* __restrict__ x,
                            const float* __restrict__ fc1_w,   // [HIDDEN, CIN]
                            const float* __restrict__ fc2_w)   // [2, HIDDEN]
{
    const int b    = blockIdx.x;
    const int tid  = threadIdx.x;
    const int warp = tid >> 5;
    const int lane = tid & 31;

    __shared__ float pooled[CIN];
    __shared__ float hid[HIDDEN];
    __shared__ float logits[2];

    for (int c = warp; c < CIN; c += 8) {
        const float* xp = x + ((size_t)b * CIN + c) * HWPIX;
        float s = 0.f;
        for (int i = lane; i < HWPIX; i += 32) s += xp[i];
        #pragma unroll
        for (int off = 16; off; off >>= 1) s += __shfl_xor_sync(0xffffffffu, s, off);
        if (lane == 0) pooled[c] = s * (1.0f / (float)HWPIX);
    }
    __syncthreads();

    if (tid < HIDDEN) {
        const float* fw = fc1_w + tid * CIN;
        float h = 0.f;
        #pragma unroll 4
        for (int c = 0; c < CIN; ++c) h += pooled[c] * fw[c];
        hid[tid] = fmaxf(h, 0.f);
    }
    __syncthreads();

    if (tid < 2) {
        const float* fw = fc2_w + tid * HIDDEN;
        float l = 0.f;
        #pragma unroll
        for (int j = 0; j < HIDDEN; ++j) l += hid[j] * fw[j];
        logits[tid] = l;
    }
    __syncthreads();

    if (tid == 0) {
        float l0 = logits[0] * (1.0f / TEMPERATURE);
        float l1 = logits[1] * (1.0f / TEMPERATURE);
        float m  = fmaxf(l0, l1);
        float e0 = __expf(l0 - m);
        float e1 = __expf(l1 - m);
        float inv = 1.0f / (e0 + e1);
        g_attn[b][0] = e0 * inv;
        g_attn[b][1] = e1 * inv;
    }
}

// ---------------------------------------------------------------------------
// Kernel 2: per-sample 3x3 conv with aggregated weights, fp32x2 packed math.
// Output-channel pairs (2p, 2p+1) share one packed accumulator; weights are
// staged interleaved so one LDS.64 yields the packed weight pair.
// Grid: (H/TH, OUTC/OT, BATCH). Block: (WW, TH) = 224 threads.
// ---------------------------------------------------------------------------
__global__ void __launch_bounds__(TPB)
dyn_conv_kernel(const float* __restrict__ x,
                const float* __restrict__ cw,   // [OUTC, CIN, 3, 3]
                const float* __restrict__ cb,   // [OUTC]
                const float* __restrict__ dw,   // [OUTC, CIN, 3, 3]
                const float* __restrict__ db,   // [OUTC]
                float* __restrict__ out)
{
    __shared__ float  sx[CCH][TH + 2][WW + 2];          // input halo tile
    __shared__ float2 swt2[OT / 2][CCH * 9];            // packed (o even, o odd)

    const int b     = blockIdx.z;
    const int obase = blockIdx.y * OT;
    const int hbase = blockIdx.x * TH;
    const int tx    = threadIdx.x;                // 0..55  (output col)
    const int ty    = threadIdx.y;                // 0..3   (o-group)
    const int tid   = ty * WW + tx;

    const float a0 = g_attn[b][0];
    const float a1 = g_attn[b][1];

    // acc2[r][p] packs outputs (o = ty*8 + 2p, +1) at row r.
    unsigned long long acc2[TH][4];
    #pragma unroll
    for (int r = 0; r < TH; ++r)
        #pragma unroll
        for (int p = 0; p < 4; ++p) acc2[r][p] = 0ull;

    const float* xb = x + (size_t)b * CIN * HWPIX;

    for (int ccb = 0; ccb < CIN; ccb += CCH) {
        __syncthreads();

        // Stage input tile (zero-padded halo).
        for (int i = tid; i < CCH * (TH + 2) * (WW + 2); i += TPB) {
            int c   = i / ((TH + 2) * (WW + 2));
            int rem = i % ((TH + 2) * (WW + 2));
            int rr  = rem / (WW + 2);
            int col = rem % (WW + 2);
            int hin = hbase + rr - 1;
            int win = col - 1;
            float v = 0.f;
            if (hin >= 0 && hin < HH && win >= 0 && win < WW)
                v = xb[(size_t)(ccb + c) * HWPIX + hin * WW + win];
            sx[c][rr][col] = v;
        }

        // Stage aggregated weights, interleaved by output-channel pair.
        for (int i = tid; i < (OT / 2) * CCH * 9; i += TPB) {
            int op  = i / (CCH * 9);              // pair index within tile
            int rem = i % (CCH * 9);
            int c   = rem / 9;
            int k   = rem % 9;
            size_t g0 = ((size_t)(obase + 2 * op)     * CIN + (ccb + c)) * 9 + k;
            size_t g1 = ((size_t)(obase + 2 * op + 1) * CIN + (ccb + c)) * 9 + k;
            swt2[op][rem] = make_float2(a0 * cw[g0] + a1 * dw[g0],
                                        a0 * cw[g1] + a1 * dw[g1]);
        }
        __syncthreads();

        #pragma unroll 1
        for (int c = 0; c < CCH; ++c) {
            // Broadcast-pack the 6x3 input window once per channel.
            unsigned long long xp[TH + 2][3];
            #pragma unroll
            for (int rr = 0; rr < TH + 2; ++rr)
                #pragma unroll
                for (int jj = 0; jj < 3; ++jj)
                    xp[rr][jj] = bcast2(sx[c][rr][tx + jj]);

            #pragma unroll
            for (int p = 0; p < 4; ++p) {
                const unsigned long long* wp =
                    reinterpret_cast<const unsigned long long*>(&swt2[ty * 4 + p][c * 9]);
                unsigned long long w[9];
                #pragma unroll
                for (int k = 0; k < 9; ++k) w[k] = wp[k];   // LDS.64, broadcast

                #pragma unroll
                for (int i3 = 0; i3 < 3; ++i3)
                    #pragma unroll
                    for (int j3 = 0; j3 < 3; ++j3)
                        #pragma unroll
                        for (int r = 0; r < TH; ++r)
                            fma2(acc2[r][p], xp[r + i3][j3], w[i3 * 3 + j3]);
            }
        }
    }

    // Epilogue: unpack, add aggregated bias, store.
    #pragma unroll
    for (int p = 0; p < 4; ++p) {
        int o0 = obase + ty * 8 + 2 * p;
        int o1 = o0 + 1;
        float b0 = a0 * cb[o0] + a1 * db[o0];
        float b1 = a0 * cb[o1] + a1 * db[o1];
        #pragma unroll
        for (int r = 0; r < TH; ++r) {
            float lo, hi;
            unpack2(acc2[r][p], lo, hi);
            out[(((size_t)b * OUTC + o0) * HH + (hbase + r)) * WW + tx] = lo + b0;
            out[(((size_t)b * OUTC + o1) * HH + (hbase + r)) * WW + tx] = hi + b1;
        }
    }
}

// ---------------------------------------------------------------------------
// Harness entry point.
// ---------------------------------------------------------------------------
extern "C" void kernel_launch(void* const* d_in, const int* in_sizes, int n_in,
                              void* d_out, int out_size)
{
    const float* x     = (const float*)d_in[0];
    const float* cw    = (const float*)d_in[1];
    const float* cb    = (const float*)d_in[2];
    const float* dw    = (const float*)d_in[3];
    const float* db    = (const float*)d_in[4];
    const float* fc1_w = (const float*)d_in[5];
    const float* fc2_w = (const float*)d_in[6];
    float* out = (float*)d_out;

    attn_kernel<<<BATCH, 256>>>(x, fc1_w, fc2_w);

    dim3 grid(HH / TH, OUTC / OT, BATCH);   // (14, 4, 32)
    dim3 block(WW, TH);                     // (56, 4) = 224 threads
    dyn_conv_kernel<<<grid, block>>>(x, cw, cb, dw, db, out);
}

// round 5
// speedup vs baseline: 2.6475x; 2.6475x over previous
#include <cuda_runtime.h>
#include <cuda_fp16.h>
#include <cstdint>

#define BATCH 32
#define CIN 128
#define OUTC 128
#define HIDDEN 32
#define TEMP 31.0f
#define HW 3136
#define PIXB 128
#define NPB 25          // ceil(3136/128)

// dynamic smem: bias[128] floats @0, A tile @1024 (32KB), B tile @33792 (32KB)
#define SM_BIAS 0
#define SM_A 1024
#define SM_B (1024 + 32768)
#define SM_TOT (SM_B + 32768)

__device__ float g_attn[BATCH][2];
__device__ __align__(16) __half g_xh[(size_t)BATCH * HW * CIN];          // HWC
__device__ __align__(16) __half g_wagg[(size_t)BATCH * 9 * OUTC * CIN];  // [b][t][o][c]

// swizzle for 256B rows: XOR row bits [8:11) into 16B-chunk bits [4:7)
#define SWZ(o) ((o) ^ (((o) >> 4) & 0x70))

__device__ __forceinline__ uint32_t smem_u32(const void* p) {
    uint32_t a;
    asm("{ .reg .u64 t; cvta.to.shared.u64 t, %1; cvt.u32.u64 %0, t; }" : "=r"(a) : "l"(p));
    return a;
}
__device__ __forceinline__ void ldm4(uint32_t* r, uint32_t addr) {
    asm volatile("ldmatrix.sync.aligned.m8n8.x4.shared.b16 {%0,%1,%2,%3}, [%4];"
                 : "=r"(r[0]), "=r"(r[1]), "=r"(r[2]), "=r"(r[3]) : "r"(addr));
}
__device__ __forceinline__ void mma16816(float* c, const uint32_t* a, const uint32_t* b) {
    asm volatile("mma.sync.aligned.m16n8k16.row.col.f32.f16.f16.f32 "
                 "{%0,%1,%2,%3}, {%4,%5,%6,%7}, {%8,%9}, {%0,%1,%2,%3};"
                 : "+f"(c[0]), "+f"(c[1]), "+f"(c[2]), "+f"(c[3])
                 : "r"(a[0]), "r"(a[1]), "r"(a[2]), "r"(a[3]), "r"(b[0]), "r"(b[1]));
}

// ---- prolog 1: pool -> mlp -> softmax ----
__global__ void attn_kernel(const float* __restrict__ x, const float* __restrict__ fc1_w,
                            const float* __restrict__ fc2_w) {
    const int b = blockIdx.x, tid = threadIdx.x, warp = tid >> 5, lane = tid & 31;
    __shared__ float pooled[CIN], hid[HIDDEN], logits[2];
    for (int c = warp; c < CIN; c += 8) {
        const float* xp = x + ((size_t)b * CIN + c) * HW;
        float s = 0.f;
        for (int i = lane; i < HW; i += 32) s += xp[i];
        #pragma unroll
        for (int o = 16; o; o >>= 1) s += __shfl_xor_sync(0xffffffffu, s, o);
        if (lane == 0) pooled[c] = s * (1.0f / (float)HW);
    }
    __syncthreads();
    if (tid < HIDDEN) {
        float h = 0.f;
        for (int c = 0; c < CIN; ++c) h += pooled[c] * fc1_w[tid * CIN + c];
        hid[tid] = fmaxf(h, 0.f);
    }
    __syncthreads();
    if (tid < 2) {
        float l = 0.f;
        for (int j = 0; j < HIDDEN; ++j) l += hid[j] * fc2_w[tid * HIDDEN + j];
        logits[tid] = l;
    }
    __syncthreads();
    if (tid == 0) {
        float l0 = logits[0] / TEMP, l1 = logits[1] / TEMP;
        float m = fmaxf(l0, l1), e0 = __expf(l0 - m), e1 = __expf(l1 - m);
        float inv = 1.0f / (e0 + e1);
        g_attn[b][0] = e0 * inv;
        g_attn[b][1] = e1 * inv;
    }
}

// ---- prolog 2: x (NCHW f32) -> g_xh (NHWC fp16) via smem tile transpose ----
__global__ void convx_kernel(const float* __restrict__ x) {
    __shared__ float t[32][33];
    const int b = blockIdx.z, c0 = blockIdx.y * 32, p0 = blockIdx.x * 32;
    const int tx = threadIdx.x, ty = threadIdx.y;
    t[ty][tx] = x[((size_t)b * CIN + c0 + ty) * HW + p0 + tx];   // coalesced in tx
    __syncthreads();
    g_xh[((size_t)b * HW + p0 + ty) * CIN + c0 + tx] = __float2half_rn(t[tx][ty]);
}

// ---- prolog 3: aggregate weights -> fp16, layout [b][t][o][c] ----
__global__ void aggw_kernel(const float* __restrict__ cw, const float* __restrict__ dw) {
    const int b = blockIdx.y;
    const float a0 = g_attn[b][0], a1 = g_attn[b][1];
    for (int i = blockIdx.x * blockDim.x + threadIdx.x; i < 9 * OUTC * CIN;
         i += gridDim.x * blockDim.x) {
        int c = i & 127, o = (i >> 7) & 127, t = i >> 14;
        size_t s = ((size_t)o * CIN + c) * 9 + t;
        g_wagg[(size_t)b * 9 * OUTC * CIN + i] = __float2half_rn(a0 * cw[s] + a1 * dw[s]);
    }
}

// ---- main conv: implicit GEMM on HMMA (mma.sync). grid (25,32), 256 thr ----
__global__ void __launch_bounds__(256, 2)
conv_kernel(const float* __restrict__ cb, const float* __restrict__ db,
            float* __restrict__ out) {
    extern __shared__ char sm[];
    const uint32_t smb = smem_u32(sm);
    const int tid = threadIdx.x, wid = tid >> 5, lane = tid & 31;
    const int wm = wid & 3, wn = wid >> 2;           // warp tile: 32 px x 64 oc
    const int b = blockIdx.y, pbase = blockIdx.x * PIXB;

    float* bias = (float*)(sm + SM_BIAS);
    if (tid < OUTC) bias[tid] = g_attn[b][0] * cb[tid] + g_attn[b][1] * db[tid];

    // staging coords: thread -> (row slot, 64-ch half)
    const int sp = tid >> 1, shalf = tid & 1;
    const int spix = pbase + sp;
    const int h = spix / 56, w = spix - h * 56;
    const __half* xb = g_xh + (size_t)b * HW * CIN;
    const __half* wb = g_wagg + (size_t)b * 9 * OUTC * CIN;
    const uint32_t o0 = (uint32_t)sp * 256 + (uint32_t)shalf * 128;

    float acc[2][8][4];
    #pragma unroll
    for (int mi = 0; mi < 2; ++mi)
        #pragma unroll
        for (int ni = 0; ni < 8; ++ni)
            #pragma unroll
            for (int e = 0; e < 4; ++e) acc[mi][ni][e] = 0.f;

    for (int t = 0; t < 9; ++t) {
        const int di = t / 3, dj = t - di * 3;
        const int hi = h + di - 1, wi = w + dj - 1;
        const bool ok = (spix < HW) && ((unsigned)hi < 56u) && ((unsigned)wi < 56u);
        const uint4* asrc = (const uint4*)(xb + ((size_t)(hi * 56 + wi)) * CIN + shalf * 64);
        const uint4* bsrc = (const uint4*)(wb + ((size_t)t * OUTC + sp) * CIN + shalf * 64);

        __syncthreads();   // previous tap's compute done before overwrite
        #pragma unroll
        for (int j = 0; j < 8; ++j) {
            uint4 av = ok ? asrc[j] : make_uint4(0u, 0u, 0u, 0u);
            *(uint4*)(sm + SM_A + SWZ(o0 + j * 16)) = av;
            *(uint4*)(sm + SM_B + SWZ(o0 + j * 16)) = bsrc[j];
        }
        __syncthreads();

        #pragma unroll
        for (int ks = 0; ks < 8; ++ks) {
            const uint32_t kb = (uint32_t)ks * 32 + ((lane >> 4) << 4);
            uint32_t a[2][4], bf[8][2];
            #pragma unroll
            for (int mi = 0; mi < 2; ++mi)
                ldm4(a[mi], smb + SM_A +
                     SWZ(((uint32_t)(wm * 32 + mi * 16 + (lane & 15)) << 8) + kb));
            #pragma unroll
            for (int nb = 0; nb < 4; ++nb) {
                uint32_t r[4];
                ldm4(r, smb + SM_B +
                     SWZ(((uint32_t)(wn * 64 + nb * 16 + (lane & 15)) << 8) + kb));
                bf[nb * 2][0] = r[0]; bf[nb * 2][1] = r[2];
                bf[nb * 2 + 1][0] = r[1]; bf[nb * 2 + 1][1] = r[3];
            }
            #pragma unroll
            for (int mi = 0; mi < 2; ++mi)
                #pragma unroll
                for (int ni = 0; ni < 8; ++ni)
                    mma16816(acc[mi][ni], a[mi], bf[ni]);
        }
    }

    // epilogue: fragment-direct stores + bias
    float* ob = out + (size_t)b * OUTC * HW;
    #pragma unroll
    for (int mi = 0; mi < 2; ++mi) {
        const int pr = pbase + wm * 32 + mi * 16 + (lane >> 2);
        #pragma unroll
        for (int ni = 0; ni < 8; ++ni) {
            const int oc = wn * 64 + ni * 8 + (lane & 3) * 2;
            const float b0 = bias[oc], b1 = bias[oc + 1];
            if (pr < HW) {
                ob[(size_t)oc * HW + pr]       = acc[mi][ni][0] + b0;
                ob[(size_t)(oc + 1) * HW + pr] = acc[mi][ni][1] + b1;
            }
            if (pr + 8 < HW) {
                ob[(size_t)oc * HW + pr + 8]       = acc[mi][ni][2] + b0;
                ob[(size_t)(oc + 1) * HW + pr + 8] = acc[mi][ni][3] + b1;
            }
        }
    }
}

extern "C" void kernel_launch(void* const* d_in, const int* in_sizes, int n_in,
                              void* d_out, int out_size) {
    const float* x     = (const float*)d_in[0];
    const float* cw    = (const float*)d_in[1];
    const float* cb    = (const float*)d_in[2];
    const float* dw    = (const float*)d_in[3];
    const float* db    = (const float*)d_in[4];
    const float* fc1_w = (const float*)d_in[5];
    const float* fc2_w = (const float*)d_in[6];
    float* out = (float*)d_out;

    cudaFuncSetAttribute(conv_kernel, cudaFuncAttributeMaxDynamicSharedMemorySize, SM_TOT);

    attn_kernel<<<BATCH, 256>>>(x, fc1_w, fc2_w);
    convx_kernel<<<dim3(HW / 32, CIN / 32, BATCH), dim3(32, 32)>>>(x);
    aggw_kernel<<<dim3(64, BATCH), 256>>>(cw, dw);
    conv_kernel<<<dim3(NPB, BATCH), 256, SM_TOT>>>(cb, db, out);
}

// round 6
// speedup vs baseline: 5.6244x; 2.1244x over previous
#include <cuda_runtime.h>
#include <cuda_fp16.h>
#include <cstdint>

#define BATCH 32
#define CIN 128
#define OUTC 128
#define HIDDEN 32
#define TEMP 31.0f
#define HW 3136
#define PIXB 128
#define NPB 25
#define NPBLK 98            // HW/32 pooling partial blocks

// dynamic smem: bias @0 (512B), A halo tile @1024 (348 rows * 256B), B 2 bufs
#define SM_A 1024
#define A_BYTES (348 * 256)          // 89088
#define SM_B (SM_A + A_BYTES)        // 90112
#define SM_TOT (SM_B + 2 * 32768)    // 155648

__device__ float g_attn[BATCH][2];
__device__ float g_part[BATCH * CIN * NPBLK];
__device__ __align__(16) __half g_xh[(size_t)BATCH * HW * CIN];          // NHWC
__device__ __align__(16) __half g_wagg[(size_t)BATCH * 9 * OUTC * CIN];  // [b][t][o][c]

#define SWZ(o) ((o) ^ (((o) >> 4) & 0x70))

__device__ __forceinline__ uint32_t smem_u32(const void* p) {
    uint32_t a;
    asm("{ .reg .u64 t; cvta.to.shared.u64 t, %1; cvt.u32.u64 %0, t; }" : "=r"(a) : "l"(p));
    return a;
}
__device__ __forceinline__ void ldm4(uint32_t* r, uint32_t addr) {
    asm volatile("ldmatrix.sync.aligned.m8n8.x4.shared.b16 {%0,%1,%2,%3}, [%4];"
                 : "=r"(r[0]), "=r"(r[1]), "=r"(r[2]), "=r"(r[3]) : "r"(addr));
}
__device__ __forceinline__ void mma16816(float* c, const uint32_t* a, const uint32_t* b) {
    asm volatile("mma.sync.aligned.m16n8k16.row.col.f32.f16.f16.f32 "
                 "{%0,%1,%2,%3}, {%4,%5,%6,%7}, {%8,%9}, {%0,%1,%2,%3};"
                 : "+f"(c[0]), "+f"(c[1]), "+f"(c[2]), "+f"(c[3])
                 : "r"(a[0]), "r"(a[1]), "r"(a[2]), "r"(a[3]), "r"(b[0]), "r"(b[1]));
}
__device__ __forceinline__ void cpasync16(uint32_t dst, const void* src, uint32_t srcsz) {
    asm volatile("cp.async.cg.shared.global [%0], [%1], 16, %2;"
                 :: "r"(dst), "l"(src), "r"(srcsz) : "memory");
}
#define CP_COMMIT() asm volatile("cp.async.commit_group;" ::: "memory")
#define CP_WAIT0()  asm volatile("cp.async.wait_group 0;" ::: "memory")

// ---- prolog 1: NCHW f32 -> NHWC fp16 transpose, fused pooling partials ----
__global__ void convx_kernel(const float* __restrict__ x) {
    __shared__ float t[32][33];
    const int b = blockIdx.z, c0 = blockIdx.y * 32, p0 = blockIdx.x * 32;
    const int tx = threadIdx.x, ty = threadIdx.y;   // (32, 8)
    #pragma unroll
    for (int k = 0; k < 4; ++k)
        t[ty + 8 * k][tx] = x[((size_t)b * CIN + c0 + ty + 8 * k) * HW + p0 + tx];
    __syncthreads();
    #pragma unroll
    for (int k = 0; k < 4; ++k)
        g_xh[((size_t)b * HW + p0 + ty + 8 * k) * CIN + c0 + tx] =
            __float2half_rn(t[tx][ty + 8 * k]);
    // pooling partials: warp ty reduces channel rows ty*4..ty*4+3 over 32 px
    #pragma unroll
    for (int k = 0; k < 4; ++k) {
        int r = ty * 4 + k;
        float s = t[r][tx];
        #pragma unroll
        for (int o = 16; o; o >>= 1) s += __shfl_xor_sync(0xffffffffu, s, o);
        if (tx == 0) g_part[((size_t)b * CIN + c0 + r) * NPBLK + blockIdx.x] = s;
    }
}

// ---- prolog 2: reduce partials -> mlp -> softmax ----
__global__ void mlp_kernel(const float* __restrict__ fc1_w, const float* __restrict__ fc2_w) {
    const int b = blockIdx.x, tid = threadIdx.x;
    __shared__ float pooled[CIN], hid[HIDDEN], logits[2];
    if (tid < CIN) {
        const float* pp = g_part + (size_t)(b * CIN + tid) * NPBLK;
        float s = 0.f;
        for (int i = 0; i < NPBLK; ++i) s += pp[i];
        pooled[tid] = s * (1.0f / (float)HW);
    }
    __syncthreads();
    if (tid < HIDDEN) {
        float h = 0.f;
        for (int c = 0; c < CIN; ++c) h += pooled[c] * fc1_w[tid * CIN + c];
        hid[tid] = fmaxf(h, 0.f);
    }
    __syncthreads();
    if (tid < 2) {
        float l = 0.f;
        for (int j = 0; j < HIDDEN; ++j) l += hid[j] * fc2_w[tid * HIDDEN + j];
        logits[tid] = l;
    }
    __syncthreads();
    if (tid == 0) {
        float l0 = logits[0] / TEMP, l1 = logits[1] / TEMP;
        float m = fmaxf(l0, l1), e0 = __expf(l0 - m), e1 = __expf(l1 - m);
        float inv = 1.0f / (e0 + e1);
        g_attn[b][0] = e0 * inv;
        g_attn[b][1] = e1 * inv;
    }
}

// ---- prolog 3: batch-shared weight aggregation -> fp16 [b][t][o][c] ----
__global__ void aggw_kernel(const float* __restrict__ cw, const float* __restrict__ dw) {
    __shared__ float cs[1152], ds[1152];
    const int o = blockIdx.x, tid = threadIdx.x;
    for (int e = tid; e < 1152; e += 256) {
        cs[e] = cw[(size_t)o * 1152 + e];   // [c][t] within this o
        ds[e] = dw[(size_t)o * 1152 + e];
    }
    __syncthreads();
    const int c = tid & 127, half = tid >> 7;   // 2 halves split the bt range
    for (int bt = half * 144; bt < (half + 1) * 144; ++bt) {
        int b = bt / 9, t = bt - b * 9;
        float a0 = g_attn[b][0], a1 = g_attn[b][1];
        float v = a0 * cs[c * 9 + t] + a1 * ds[c * 9 + t];
        g_wagg[(((size_t)b * 9 + t) * OUTC + o) * CIN + c] = __float2half_rn(v);
    }
}

// ---- main conv: implicit GEMM on HMMA, halo A tile + cp.async B pipeline ----
__global__ void __launch_bounds__(256)
conv_kernel(const float* __restrict__ cb, const float* __restrict__ db,
            float* __restrict__ out) {
    extern __shared__ char sm[];
    const uint32_t smb = smem_u32(sm);
    const int tid = threadIdx.x, wid = tid >> 5, lane = tid & 31;
    const int wm = wid & 3, wn = wid >> 2;                 // warp tile 32px x 64oc
    const int b = blockIdx.y, pbase = blockIdx.x * PIXB;
    const int h0 = pbase / 56;

    float* bias = (float*)sm;
    if (tid < OUTC) bias[tid] = g_attn[b][0] * cb[tid] + g_attn[b][1] * db[tid];

    const __half* xb = g_xh + (size_t)b * HW * CIN;
    const __half* wb = g_wagg + (size_t)b * 9 * OUTC * CIN;

    // --- stage A halo tile (348 rows x 256B) + B tap 0, async ---
    for (int e = tid; e < 348 * 16; e += 256) {
        int rr = e >> 4, ch = e & 15;
        int ih = h0 - 1 + rr / 58, iw = rr % 58 - 1;
        bool ok = ((unsigned)ih < 56u) && ((unsigned)iw < 56u);
        const void* src = xb + (ok ? ((size_t)(ih * 56 + iw) * CIN + ch * 8) : 0);
        cpasync16(smb + SM_A + SWZ((uint32_t)rr * 256 + ch * 16), src, ok ? 16u : 0u);
    }
    #pragma unroll
    for (int i = 0; i < 8; ++i) {
        int e = tid + i * 256, o = e >> 4, ch = e & 15;
        cpasync16(smb + SM_B + SWZ((uint32_t)o * 256 + ch * 16),
                  wb + (size_t)o * CIN + ch * 8, 16u);
    }
    CP_COMMIT();

    // per-thread A row coords (mi = 0,1)
    int hh[2], ww[2];
    #pragma unroll
    for (int mi = 0; mi < 2; ++mi) {
        int p = pbase + wm * 32 + mi * 16 + (lane & 15);
        hh[mi] = p / 56;
        ww[mi] = p - hh[mi] * 56;
    }

    float acc[2][8][4];
    #pragma unroll
    for (int mi = 0; mi < 2; ++mi)
        #pragma unroll
        for (int ni = 0; ni < 8; ++ni)
            #pragma unroll
            for (int e = 0; e < 4; ++e) acc[mi][ni][e] = 0.f;

    // B lane base offsets (constant across taps)
    uint32_t brow[4];
    #pragma unroll
    for (int nb = 0; nb < 4; ++nb)
        brow[nb] = (uint32_t)(wn * 64 + nb * 16 + (lane & 15)) * 256;
    const uint32_t ksub = (uint32_t)((lane >> 4) << 4);

    CP_WAIT0();
    __syncthreads();

    for (int t = 0; t < 9; ++t) {
        // prefetch next tap's B into alternate buffer
        if (t < 8) {
            const __half* wn8 = wb + (size_t)(t + 1) * OUTC * CIN;
            uint32_t buf = smb + SM_B + (uint32_t)(((t + 1) & 1) * 32768);
            #pragma unroll
            for (int i = 0; i < 8; ++i) {
                int e = tid + i * 256, o = e >> 4, ch = e & 15;
                cpasync16(buf + SWZ((uint32_t)o * 256 + ch * 16),
                          wn8 + (size_t)o * CIN + ch * 8, 16u);
            }
            CP_COMMIT();
        }

        const int di = t / 3, dj = t - di * 3;
        uint32_t abase[2], axr[2];
        #pragma unroll
        for (int mi = 0; mi < 2; ++mi) {
            uint32_t rr = (uint32_t)((hh[mi] - h0 + di) * 58 + ww[mi] + dj);
            abase[mi] = smb + SM_A + rr * 256;
            axr[mi] = (rr & 7) << 4;
        }
        const uint32_t bbuf = smb + SM_B + (uint32_t)((t & 1) * 32768);

        #pragma unroll
        for (int ks = 0; ks < 8; ++ks) {
            const uint32_t kb = (uint32_t)ks * 32 + ksub;
            uint32_t a[2][4], bf[8][2];
            #pragma unroll
            for (int mi = 0; mi < 2; ++mi)
                ldm4(a[mi], abase[mi] + (kb ^ axr[mi]));
            #pragma unroll
            for (int nb = 0; nb < 4; ++nb) {
                uint32_t r[4];
                ldm4(r, bbuf + SWZ(brow[nb] + kb));
                bf[nb * 2][0] = r[0]; bf[nb * 2][1] = r[2];
                bf[nb * 2 + 1][0] = r[1]; bf[nb * 2 + 1][1] = r[3];
            }
            #pragma unroll
            for (int mi = 0; mi < 2; ++mi)
                #pragma unroll
                for (int ni = 0; ni < 8; ++ni)
                    mma16816(acc[mi][ni], a[mi], bf[ni]);
        }

        if (t < 8) {
            CP_WAIT0();
            __syncthreads();
        }
    }

    // epilogue
    float* ob = out + (size_t)b * OUTC * HW;
    #pragma unroll
    for (int mi = 0; mi < 2; ++mi) {
        const int pr = pbase + wm * 32 + mi * 16 + (lane >> 2);
        #pragma unroll
        for (int ni = 0; ni < 8; ++ni) {
            const int oc = wn * 64 + ni * 8 + (lane & 3) * 2;
            const float b0 = bias[oc], b1 = bias[oc + 1];
            if (pr < HW) {
                ob[(size_t)oc * HW + pr]       = acc[mi][ni][0] + b0;
                ob[(size_t)(oc + 1) * HW + pr] = acc[mi][ni][1] + b1;
            }
            if (pr + 8 < HW) {
                ob[(size_t)oc * HW + pr + 8]       = acc[mi][ni][2] + b0;
                ob[(size_t)(oc + 1) * HW + pr + 8] = acc[mi][ni][3] + b1;
            }
        }
    }
}

extern "C" void kernel_launch(void* const* d_in, const int* in_sizes, int n_in,
                              void* d_out, int out_size) {
    const float* x     = (const float*)d_in[0];
    const float* cw    = (const float*)d_in[1];
    const float* cb    = (const float*)d_in[2];
    const float* dw    = (const float*)d_in[3];
    const float* db    = (const float*)d_in[4];
    const float* fc1_w = (const float*)d_in[5];
    const float* fc2_w = (const float*)d_in[6];
    float* out = (float*)d_out;

    cudaFuncSetAttribute(conv_kernel, cudaFuncAttributeMaxDynamicSharedMemorySize, SM_TOT);

    convx_kernel<<<dim3(NPBLK, CIN / 32, BATCH), dim3(32, 8)>>>(x);
    mlp_kernel<<<BATCH, 128>>>(fc1_w, fc2_w);
    aggw_kernel<<<OUTC, 256>>>(cw, dw);
    conv_kernel<<<dim3(NPB, BATCH), 256, SM_TOT>>>(cb, db, out);
}

// round 7
// speedup vs baseline: 5.9597x; 1.0596x over previous
#include <cuda_runtime.h>
#include <cuda_fp16.h>
#include <cstdint>

#define BATCH 32
#define CIN 128
#define OUTC 128
#define HIDDEN 32
#define TEMP 31.0f
#define HW 3136
#define PIXB 256
#define NPB 13
#define NPBLK 98

// dynamic smem: bias @0, A halo tile @1024 (464 rows * 256B), B 2 bufs
#define SM_A 1024
#define A_BYTES (464 * 256)          // 118784
#define SM_B (SM_A + A_BYTES)        // 119808
#define SM_TOT (SM_B + 2 * 32768)    // 185344

__device__ float g_attn[BATCH][2];
__device__ float g_part[BATCH * CIN * NPBLK];
__device__ __align__(16) __half g_xh[(size_t)BATCH * HW * CIN];          // NHWC
__device__ __align__(16) __half g_wagg[(size_t)BATCH * 9 * OUTC * CIN];  // [b][t][o][c]

#define SWZ(o) ((o) ^ (((o) >> 4) & 0x70))

__device__ __forceinline__ uint32_t smem_u32(const void* p) {
    uint32_t a;
    asm("{ .reg .u64 t; cvta.to.shared.u64 t, %1; cvt.u32.u64 %0, t; }" : "=r"(a) : "l"(p));
    return a;
}
__device__ __forceinline__ void ldm4(uint32_t* r, uint32_t addr) {
    asm volatile("ldmatrix.sync.aligned.m8n8.x4.shared.b16 {%0,%1,%2,%3}, [%4];"
                 : "=r"(r[0]), "=r"(r[1]), "=r"(r[2]), "=r"(r[3]) : "r"(addr));
}
__device__ __forceinline__ void mma16816(float* c, const uint32_t* a, const uint32_t* b) {
    asm volatile("mma.sync.aligned.m16n8k16.row.col.f32.f16.f16.f32 "
                 "{%0,%1,%2,%3}, {%4,%5,%6,%7}, {%8,%9}, {%0,%1,%2,%3};"
                 : "+f"(c[0]), "+f"(c[1]), "+f"(c[2]), "+f"(c[3])
                 : "r"(a[0]), "r"(a[1]), "r"(a[2]), "r"(a[3]), "r"(b[0]), "r"(b[1]));
}
__device__ __forceinline__ void cpasync16(uint32_t dst, const void* src, uint32_t srcsz) {
    asm volatile("cp.async.cg.shared.global [%0], [%1], 16, %2;"
                 :: "r"(dst), "l"(src), "r"(srcsz) : "memory");
}
#define CP_COMMIT() asm volatile("cp.async.commit_group;" ::: "memory")
#define CP_WAIT0()  asm volatile("cp.async.wait_group 0;" ::: "memory")

// ---- prolog 1: NCHW f32 -> NHWC fp16 transpose, fused pooling partials ----
__global__ void convx_kernel(const float* __restrict__ x) {
    __shared__ float t[32][33];
    const int b = blockIdx.z, c0 = blockIdx.y * 32, p0 = blockIdx.x * 32;
    const int tx = threadIdx.x, ty = threadIdx.y;   // (32, 8)
    #pragma unroll
    for (int k = 0; k < 4; ++k)
        t[ty + 8 * k][tx] = x[((size_t)b * CIN + c0 + ty + 8 * k) * HW + p0 + tx];
    __syncthreads();
    #pragma unroll
    for (int k = 0; k < 4; ++k)
        g_xh[((size_t)b * HW + p0 + ty + 8 * k) * CIN + c0 + tx] =
            __float2half_rn(t[tx][ty + 8 * k]);
    #pragma unroll
    for (int k = 0; k < 4; ++k) {
        int r = ty * 4 + k;
        float s = t[r][tx];
        #pragma unroll
        for (int o = 16; o; o >>= 1) s += __shfl_xor_sync(0xffffffffu, s, o);
        if (tx == 0) g_part[((size_t)b * CIN + c0 + r) * NPBLK + blockIdx.x] = s;
    }
}

// ---- prolog 2: reduce partials -> mlp -> softmax ----
__global__ void mlp_kernel(const float* __restrict__ fc1_w, const float* __restrict__ fc2_w) {
    const int b = blockIdx.x, tid = threadIdx.x;
    __shared__ float pooled[CIN], hid[HIDDEN], logits[2];
    if (tid < CIN) {
        const float* pp = g_part + (size_t)(b * CIN + tid) * NPBLK;
        float s = 0.f;
        for (int i = 0; i < NPBLK; ++i) s += pp[i];
        pooled[tid] = s * (1.0f / (float)HW);
    }
    __syncthreads();
    if (tid < HIDDEN) {
        float h = 0.f;
        for (int c = 0; c < CIN; ++c) h += pooled[c] * fc1_w[tid * CIN + c];
        hid[tid] = fmaxf(h, 0.f);
    }
    __syncthreads();
    if (tid < 2) {
        float l = 0.f;
        for (int j = 0; j < HIDDEN; ++j) l += hid[j] * fc2_w[tid * HIDDEN + j];
        logits[tid] = l;
    }
    __syncthreads();
    if (tid == 0) {
        float l0 = logits[0] / TEMP, l1 = logits[1] / TEMP;
        float m = fmaxf(l0, l1), e0 = __expf(l0 - m), e1 = __expf(l1 - m);
        float inv = 1.0f / (e0 + e1);
        g_attn[b][0] = e0 * inv;
        g_attn[b][1] = e1 * inv;
    }
}

// ---- prolog 3: batch-shared weight aggregation -> fp16 [b][t][o][c] ----
__global__ void aggw_kernel(const float* __restrict__ cw, const float* __restrict__ dw) {
    __shared__ float cs[1152], ds[1152];
    const int o = blockIdx.x, tid = threadIdx.x;
    for (int e = tid; e < 1152; e += 256) {
        cs[e] = cw[(size_t)o * 1152 + e];
        ds[e] = dw[(size_t)o * 1152 + e];
    }
    __syncthreads();
    const int c = tid & 127, half = tid >> 7;
    for (int bt = half * 144; bt < (half + 1) * 144; ++bt) {
        int b = bt / 9, t = bt - b * 9;
        float a0 = g_attn[b][0], a1 = g_attn[b][1];
        float v = a0 * cs[c * 9 + t] + a1 * ds[c * 9 + t];
        g_wagg[(((size_t)b * 9 + t) * OUTC + o) * CIN + c] = __float2half_rn(v);
    }
}

// ---- main conv: HMMA implicit GEMM, 256px x 128oc CTA, 512 threads ----
__global__ void __launch_bounds__(512)
conv_kernel(const float* __restrict__ cb, const float* __restrict__ db,
            float* __restrict__ out) {
    extern __shared__ char sm[];
    const uint32_t smb = smem_u32(sm);
    const int tid = threadIdx.x, wid = tid >> 5, lane = tid & 31;
    const int wm = wid & 7, wn = wid >> 3;               // 8 m-warps x 2 n-warps
    const int b = blockIdx.y, pbase = blockIdx.x * PIXB;
    const int h0 = pbase / 56;

    float* bias = (float*)sm;
    if (tid < OUTC) bias[tid] = g_attn[b][0] * cb[tid] + g_attn[b][1] * db[tid];

    const __half* xb = g_xh + (size_t)b * HW * CIN;
    const __half* wb = g_wagg + (size_t)b * 9 * OUTC * CIN;

    // --- stage A halo tile (464 rows x 256B): image rows h0-1 .. h0+6 ---
    for (int e = tid; e < 464 * 16; e += 512) {
        int rr = e >> 4, ch = e & 15;
        int ih = h0 - 1 + rr / 58, iw = rr % 58 - 1;
        bool ok = ((unsigned)ih < 56u) && ((unsigned)iw < 56u);
        const void* src = xb + (ok ? ((size_t)(ih * 56 + iw) * CIN + ch * 8) : 0);
        cpasync16(smb + SM_A + SWZ((uint32_t)rr * 256 + ch * 16), src, ok ? 16u : 0u);
    }
    #pragma unroll
    for (int i = 0; i < 4; ++i) {
        int e = tid + i * 512, o = e >> 4, ch = e & 15;
        cpasync16(smb + SM_B + SWZ((uint32_t)o * 256 + ch * 16),
                  wb + (size_t)o * CIN + ch * 8, 16u);
    }
    CP_COMMIT();

    int hh[2], ww[2];
    #pragma unroll
    for (int mi = 0; mi < 2; ++mi) {
        int p = pbase + wm * 32 + mi * 16 + (lane & 15);
        hh[mi] = p / 56;
        ww[mi] = p - hh[mi] * 56;
    }

    float acc[2][8][4];
    #pragma unroll
    for (int mi = 0; mi < 2; ++mi)
        #pragma unroll
        for (int ni = 0; ni < 8; ++ni)
            #pragma unroll
            for (int e = 0; e < 4; ++e) acc[mi][ni][e] = 0.f;

    uint32_t brow[4], bxr[4];
    #pragma unroll
    for (int nb = 0; nb < 4; ++nb) {
        brow[nb] = (uint32_t)(wn * 64 + nb * 16 + (lane & 15)) * 256;
        bxr[nb] = (brow[nb] >> 4) & 0x70;
    }
    const uint32_t ksub = (uint32_t)((lane >> 4) << 4);

    CP_WAIT0();
    __syncthreads();

    for (int t = 0; t < 9; ++t) {
        if (t < 8) {
            const __half* wnx = wb + (size_t)(t + 1) * OUTC * CIN;
            uint32_t buf = smb + SM_B + (uint32_t)(((t + 1) & 1) * 32768);
            #pragma unroll
            for (int i = 0; i < 4; ++i) {
                int e = tid + i * 512, o = e >> 4, ch = e & 15;
                cpasync16(buf + SWZ((uint32_t)o * 256 + ch * 16),
                          wnx + (size_t)o * CIN + ch * 8, 16u);
            }
            CP_COMMIT();
        }

        const int di = t / 3, dj = t - di * 3;
        uint32_t abase[2], axr[2];
        #pragma unroll
        for (int mi = 0; mi < 2; ++mi) {
            uint32_t rr = (uint32_t)((hh[mi] - h0 + di) * 58 + ww[mi] + dj);
            abase[mi] = smb + SM_A + rr * 256;
            axr[mi] = (rr & 7) << 4;
        }
        const uint32_t bbuf = smb + SM_B + (uint32_t)((t & 1) * 32768);

        #pragma unroll
        for (int ks = 0; ks < 8; ++ks) {
            const uint32_t kb = (uint32_t)ks * 32 + ksub;
            uint32_t a[2][4], bf[8][2];
            #pragma unroll
            for (int mi = 0; mi < 2; ++mi)
                ldm4(a[mi], abase[mi] + (kb ^ axr[mi]));
            #pragma unroll
            for (int nb = 0; nb < 4; ++nb) {
                uint32_t r[4];
                ldm4(r, bbuf + brow[nb] + (kb ^ bxr[nb]));
                bf[nb * 2][0] = r[0]; bf[nb * 2][1] = r[2];
                bf[nb * 2 + 1][0] = r[1]; bf[nb * 2 + 1][1] = r[3];
            }
            #pragma unroll
            for (int mi = 0; mi < 2; ++mi)
                #pragma unroll
                for (int ni = 0; ni < 8; ++ni)
                    mma16816(acc[mi][ni], a[mi], bf[ni]);
        }

        if (t < 8) {
            CP_WAIT0();
            __syncthreads();
        }
    }

    // ---- epilogue: stage C through smem (overlays A tile), coalesced STG ----
    float* csm = (float*)(sm + SM_A);          // [64 oc][260 px floats]
    float* ob = out + (size_t)b * OUTC * HW;
    __syncthreads();                            // A-tile reads done
    #pragma unroll
    for (int nh = 0; nh < 2; ++nh) {
        if (nh) __syncthreads();                // half-0 stores done
        if (wn == nh) {
            #pragma unroll
            for (int mi = 0; mi < 2; ++mi) {
                const int prl = wm * 32 + mi * 16 + (lane >> 2);
                #pragma unroll
                for (int ni = 0; ni < 8; ++ni) {
                    const int ocl = ni * 8 + (lane & 3) * 2;
                    csm[ocl * 260 + prl]           = acc[mi][ni][0];
                    csm[(ocl + 1) * 260 + prl]     = acc[mi][ni][1];
                    csm[ocl * 260 + prl + 8]       = acc[mi][ni][2];
                    csm[(ocl + 1) * 260 + prl + 8] = acc[mi][ni][3];
                }
            }
        }
        __syncthreads();
        #pragma unroll
        for (int i = 0; i < 8; ++i) {
            int idx = tid + i * 512;            // 0..4095 = ocl*64 + px4
            int ocl = idx >> 6, px4 = idx & 63;
            int pix = pbase + px4 * 4;
            if (pix < HW) {
                float4 v = *(float4*)&csm[ocl * 260 + px4 * 4];
                float bb = bias[nh * 64 + ocl];
                v.x += bb; v.y += bb; v.z += bb; v.w += bb;
                *(float4*)&ob[(size_t)(nh * 64 + ocl) * HW + pix] = v;
            }
        }
    }
}

extern "C" void kernel_launch(void* const* d_in, const int* in_sizes, int n_in,
                              void* d_out, int out_size) {
    const float* x     = (const float*)d_in[0];
    const float* cw    = (const float*)d_in[1];
    const float* cb    = (const float*)d_in[2];
    const float* dw    = (const float*)d_in[3];
    const float* db    = (const float*)d_in[4];
    const float* fc1_w = (const float*)d_in[5];
    const float* fc2_w = (const float*)d_in[6];
    float* out = (float*)d_out;

    cudaFuncSetAttribute(conv_kernel, cudaFuncAttributeMaxDynamicSharedMemorySize, SM_TOT);

    convx_kernel<<<dim3(NPBLK, CIN / 32, BATCH), dim3(32, 8)>>>(x);
    mlp_kernel<<<BATCH, 128>>>(fc1_w, fc2_w);
    aggw_kernel<<<OUTC, 256>>>(cw, dw);
    conv_kernel<<<dim3(NPB, BATCH), 512, SM_TOT>>>(cb, db, out);
}

// round 9
// speedup vs baseline: 6.1020x; 1.0239x over previous
#include <cuda_runtime.h>
#include <cuda_fp16.h>
#include <cstdint>

#define BATCH 32
#define CIN 128
#define OUTC 128
#define HIDDEN 32
#define TEMP 31.0f
#define HW 3136
#define PIXB 128
#define NPB 25
#define NPBLK 98

// dynamic smem: bias @0, A halo (348 rows * 128B = 6 image rows) @1024, B 2x16KB
#define SM_A 1024
#define A_ROWS 348
#define A_BYTES (A_ROWS * 128)       // 44544
#define SM_B (SM_A + A_BYTES)        // 45568
#define SM_TOT (SM_B + 2 * 16384)    // 78336

__device__ float g_attn[BATCH][2];
__device__ float g_part[BATCH * CIN * NPBLK];
__device__ __align__(16) __half g_xh[(size_t)BATCH * HW * CIN];          // NHWC
__device__ __align__(16) __half g_wagg[(size_t)BATCH * 9 * OUTC * CIN];  // [b][t][o][c]

// swizzle for 128B rows: XOR 16B-chunk bits [4:7) with row bits [7:10)
#define SWZ(o) ((o) ^ (((o) >> 3) & 0x70))

__device__ __forceinline__ uint32_t smem_u32(const void* p) {
    uint32_t a;
    asm("{ .reg .u64 t; cvta.to.shared.u64 t, %1; cvt.u32.u64 %0, t; }" : "=r"(a) : "l"(p));
    return a;
}
__device__ __forceinline__ void ldm4(uint32_t* r, uint32_t addr) {
    asm volatile("ldmatrix.sync.aligned.m8n8.x4.shared.b16 {%0,%1,%2,%3}, [%4];"
                 : "=r"(r[0]), "=r"(r[1]), "=r"(r[2]), "=r"(r[3]) : "r"(addr));
}
__device__ __forceinline__ void mma16816(float* c, const uint32_t* a, const uint32_t* b) {
    asm volatile("mma.sync.aligned.m16n8k16.row.col.f32.f16.f16.f32 "
                 "{%0,%1,%2,%3}, {%4,%5,%6,%7}, {%8,%9}, {%0,%1,%2,%3};"
                 : "+f"(c[0]), "+f"(c[1]), "+f"(c[2]), "+f"(c[3])
                 : "r"(a[0]), "r"(a[1]), "r"(a[2]), "r"(a[3]), "r"(b[0]), "r"(b[1]));
}
__device__ __forceinline__ void cpasync16(uint32_t dst, const void* src, uint32_t srcsz) {
    asm volatile("cp.async.cg.shared.global [%0], [%1], 16, %2;"
                 :: "r"(dst), "l"(src), "r"(srcsz) : "memory");
}
#define CP_COMMIT() asm volatile("cp.async.commit_group;" ::: "memory")
#define CP_WAIT0()  asm volatile("cp.async.wait_group 0;" ::: "memory")

// ---- prolog 1: NCHW f32 -> NHWC fp16 (half2 stores) + pooling partials ----
__global__ void convx_kernel(const float* __restrict__ x) {
    __shared__ float t[64][33];
    const int b = blockIdx.z, c0 = blockIdx.y * 64, p0 = blockIdx.x * 32;
    const int tx = threadIdx.x, ty = threadIdx.y;   // (32, 8)
    #pragma unroll
    for (int k = 0; k < 8; ++k)
        t[ty + 8 * k][tx] = x[((size_t)b * CIN + c0 + ty + 8 * k) * HW + p0 + tx];
    __syncthreads();
    __half2* xh2 = (__half2*)g_xh;
    #pragma unroll
    for (int kk = 0; kk < 4; ++kk) {
        int p = ty + 8 * kk;
        xh2[((size_t)b * HW + p0 + p) * 64 + (c0 >> 1) + tx] =
            __floats2half2_rn(t[2 * tx][p], t[2 * tx + 1][p]);
    }
    #pragma unroll
    for (int k = 0; k < 8; ++k) {
        int c = ty * 8 + k;
        float s = t[c][tx];
        #pragma unroll
        for (int o = 16; o; o >>= 1) s += __shfl_xor_sync(0xffffffffu, s, o);
        if (tx == 0) g_part[((size_t)b * CIN + c0 + c) * NPBLK + blockIdx.x] = s;
    }
}

// ---- prolog 2: reduce partials -> mlp -> softmax ----
__global__ void mlp_kernel(const float* __restrict__ fc1_w, const float* __restrict__ fc2_w) {
    const int b = blockIdx.x, tid = threadIdx.x;
    __shared__ float pooled[CIN], hid[HIDDEN], logits[2];
    if (tid < CIN) {
        const float* pp = g_part + (size_t)(b * CIN + tid) * NPBLK;
        float s = 0.f;
        for (int i = 0; i < NPBLK; ++i) s += pp[i];
        pooled[tid] = s * (1.0f / (float)HW);
    }
    __syncthreads();
    if (tid < HIDDEN) {
        float h = 0.f;
        for (int c = 0; c < CIN; ++c) h += pooled[c] * fc1_w[tid * CIN + c];
        hid[tid] = fmaxf(h, 0.f);
    }
    __syncthreads();
    if (tid < 2) {
        float l = 0.f;
        for (int j = 0; j < HIDDEN; ++j) l += hid[j] * fc2_w[tid * HIDDEN + j];
        logits[tid] = l;
    }
    __syncthreads();
    if (tid == 0) {
        float l0 = logits[0] / TEMP, l1 = logits[1] / TEMP;
        float m = fmaxf(l0, l1), e0 = __expf(l0 - m), e1 = __expf(l1 - m);
        float inv = 1.0f / (e0 + e1);
        g_attn[b][0] = e0 * inv;
        g_attn[b][1] = e1 * inv;
    }
}

// ---- prolog 3: weight aggregation -> fp16 [b][t][o][c] (half2 stores) ----
__global__ void aggw_kernel(const float* __restrict__ cw, const float* __restrict__ dw) {
    __shared__ float cs[1152], ds[1152];
    const int o = blockIdx.x, tid = threadIdx.x;
    for (int e = tid; e < 1152; e += 256) {
        cs[e] = cw[(size_t)o * 1152 + e];
        ds[e] = dw[(size_t)o * 1152 + e];
    }
    __syncthreads();
    const int c2 = tid & 63, q = tid >> 6;
    __half2* wg2 = (__half2*)g_wagg;
    for (int bt = q * 72; bt < (q + 1) * 72; ++bt) {
        int b = bt / 9, t = bt - b * 9;
        float a0 = g_attn[b][0], a1 = g_attn[b][1];
        float v0 = a0 * cs[(2 * c2) * 9 + t] + a1 * ds[(2 * c2) * 9 + t];
        float v1 = a0 * cs[(2 * c2 + 1) * 9 + t] + a1 * ds[(2 * c2 + 1) * 9 + t];
        wg2[(((size_t)b * 9 + t) * OUTC + o) * 64 + c2] = __floats2half2_rn(v0, v1);
    }
}

// ---- main conv: HMMA implicit GEMM, 128px x 128oc CTA, channel-split K ----
__global__ void __launch_bounds__(256, 2)
conv_kernel(const float* __restrict__ cb, const float* __restrict__ db,
            float* __restrict__ out) {
    extern __shared__ char sm[];
    const uint32_t smb = smem_u32(sm);
    const int tid = threadIdx.x, wid = tid >> 5, lane = tid & 31;
    const int wm = wid & 3, wn = wid >> 2;               // 4 m-warps x 2 n-warps
    const int b = blockIdx.y, pbase = blockIdx.x * PIXB;
    const int h0 = pbase / 56;

    float* bias = (float*)sm;
    if (tid < OUTC) bias[tid] = g_attn[b][0] * cb[tid] + g_attn[b][1] * db[tid];

    const __half* xb = g_xh + (size_t)b * HW * CIN;
    const __half* wb = g_wagg + (size_t)b * 9 * OUTC * CIN;

    // per-thread A pixel coords (clamped for out-of-range tail pixels)
    int hh[2], ww[2];
    #pragma unroll
    for (int mi = 0; mi < 2; ++mi) {
        int p = pbase + wm * 32 + mi * 16 + (lane & 15);
        if (p >= HW) p = HW - 1;
        hh[mi] = p / 56;
        ww[mi] = p - hh[mi] * 56;
    }

    float acc[2][8][4];
    #pragma unroll
    for (int mi = 0; mi < 2; ++mi)
        #pragma unroll
        for (int ni = 0; ni < 8; ++ni)
            #pragma unroll
            for (int e = 0; e < 4; ++e) acc[mi][ni][e] = 0.f;

    uint32_t brow[4];
    #pragma unroll
    for (int nb = 0; nb < 4; ++nb)
        brow[nb] = (uint32_t)(wn * 64 + nb * 16 + (lane & 15)) * 128;
    const uint32_t bxr = (uint32_t)(lane & 7) << 4;
    const uint32_t ksub = (uint32_t)((lane >> 4) << 4);

    // initial stage: A half 0 + B stage 0
    for (int e = tid; e < A_ROWS * 8; e += 256) {
        int rr = e >> 3, ch = e & 7;
        int ih = h0 - 1 + rr / 58, iw = rr % 58 - 1;
        bool ok = ((unsigned)ih < 56u) && ((unsigned)iw < 56u);
        const void* src = xb + (ok ? ((size_t)(ih * 56 + iw) * CIN + ch * 8) : 0);
        cpasync16(smb + SM_A + SWZ((uint32_t)rr * 128 + ch * 16), src, ok ? 16u : 0u);
    }
    #pragma unroll
    for (int i = 0; i < 4; ++i) {
        int e = tid + i * 256, o = e >> 3, ch = e & 7;
        cpasync16(smb + SM_B + SWZ((uint32_t)o * 128 + ch * 16),
                  wb + (size_t)o * CIN + ch * 8, 16u);
    }
    CP_COMMIT();
    CP_WAIT0();
    __syncthreads();

    for (int s = 0; s < 18; ++s) {
        const int hf = s / 9, t = s - hf * 9;
        // prefetch next stage's B
        if (s < 17) {
            const int sn = s + 1, hfn = sn / 9, tn = sn - hfn * 9;
            const __half* wsrc = wb + (size_t)tn * OUTC * CIN + hfn * 64;
            uint32_t buf = smb + SM_B + (uint32_t)((sn & 1) * 16384);
            #pragma unroll
            for (int i = 0; i < 4; ++i) {
                int e = tid + i * 256, o = e >> 3, ch = e & 7;
                cpasync16(buf + SWZ((uint32_t)o * 128 + ch * 16),
                          wsrc + (size_t)o * CIN + ch * 8, 16u);
            }
            CP_COMMIT();
        }

        const int di = t / 3, dj = t - di * 3;
        uint32_t abase[2], axr[2];
        #pragma unroll
        for (int mi = 0; mi < 2; ++mi) {
            uint32_t rr = (uint32_t)((hh[mi] - h0 + di) * 58 + ww[mi] + dj);
            abase[mi] = smb + SM_A + rr * 128;
            axr[mi] = (rr & 7) << 4;
        }
        const uint32_t bbuf = smb + SM_B + (uint32_t)((s & 1) * 16384);

        #pragma unroll
        for (int ks = 0; ks < 4; ++ks) {
            const uint32_t kb = (uint32_t)ks * 32 + ksub;
            uint32_t a[2][4], bf[8][2];
            #pragma unroll
            for (int mi = 0; mi < 2; ++mi)
                ldm4(a[mi], abase[mi] + (kb ^ axr[mi]));
            #pragma unroll
            for (int nb = 0; nb < 4; ++nb) {
                uint32_t r[4];
                ldm4(r, bbuf + brow[nb] + (kb ^ bxr));
                bf[nb * 2][0] = r[0]; bf[nb * 2][1] = r[2];
                bf[nb * 2 + 1][0] = r[1]; bf[nb * 2 + 1][1] = r[3];
            }
            #pragma unroll
            for (int mi = 0; mi < 2; ++mi)
                #pragma unroll
                for (int ni = 0; ni < 8; ++ni)
                    mma16816(acc[mi][ni], a[mi], bf[ni]);
        }

        if (s == 8) {
            // restage A for channel half 1 (all half-0 reads done)
            __syncthreads();
            for (int e = tid; e < A_ROWS * 8; e += 256) {
                int rr = e >> 3, ch = e & 7;
                int ih = h0 - 1 + rr / 58, iw = rr % 58 - 1;
                bool ok = ((unsigned)ih < 56u) && ((unsigned)iw < 56u);
                const void* src = xb + (ok ? ((size_t)(ih * 56 + iw) * CIN + 64 + ch * 8) : 0);
                cpasync16(smb + SM_A + SWZ((uint32_t)rr * 128 + ch * 16), src, ok ? 16u : 0u);
            }
            CP_COMMIT();
        }
        if (s < 17) {
            CP_WAIT0();
            __syncthreads();
        }
    }

    // ---- epilogue: stage C through smem (overlays A/B), coalesced STG ----
    float* csm = (float*)(sm + SM_A);          // [128 oc][132 px floats]
    float* ob = out + (size_t)b * OUTC * HW;
    __syncthreads();
    #pragma unroll
    for (int mi = 0; mi < 2; ++mi) {
        const int prl = wm * 32 + mi * 16 + (lane >> 2);
        #pragma unroll
        for (int ni = 0; ni < 8; ++ni) {
            const int ocl = wn * 64 + ni * 8 + (lane & 3) * 2;
            csm[ocl * 132 + prl]           = acc[mi][ni][0];
            csm[(ocl + 1) * 132 + prl]     = acc[mi][ni][1];
            csm[ocl * 132 + prl + 8]       = acc[mi][ni][2];
            csm[(ocl + 1) * 132 + prl + 8] = acc[mi][ni][3];
        }
    }
    __syncthreads();
    #pragma unroll
    for (int i = 0; i < 16; ++i) {
        int idx = tid + i * 256;               // ocl*32 + px4
        int ocl = idx >> 5, px4 = idx & 31;
        int pix = pbase + px4 * 4;
        if (pix < HW) {
            float4 v = *(float4*)&csm[ocl * 132 + px4 * 4];
            float bb = bias[ocl];
            v.x += bb; v.y += bb; v.z += bb; v.w += bb;
            *(float4*)&ob[(size_t)ocl * HW + pix] = v;
        }
    }
}

extern "C" void kernel_launch(void* const* d_in, const int* in_sizes, int n_in,
                              void* d_out, int out_size) {
    const float* x     = (const float*)d_in[0];
    const float* cw    = (const float*)d_in[1];
    const float* cb    = (const float*)d_in[2];
    const float* dw    = (const float*)d_in[3];
    const float* db    = (const float*)d_in[4];
    const float* fc1_w = (const float*)d_in[5];
    const float* fc2_w = (const float*)d_in[6];
    float* out = (float*)d_out;

    cudaFuncSetAttribute(conv_kernel, cudaFuncAttributeMaxDynamicSharedMemorySize, SM_TOT);

    convx_kernel<<<dim3(NPBLK, 2, BATCH), dim3(32, 8)>>>(x);
    mlp_kernel<<<BATCH, 128>>>(fc1_w, fc2_w);
    aggw_kernel<<<OUTC, 256>>>(cw, dw);
    conv_kernel<<<dim3(NPB, BATCH), 256, SM_TOT>>>(cb, db, out);
}